// round 9
// baseline (speedup 1.0000x reference)
#include <cuda_runtime.h>
#include <cuda_bf16.h>
#include <cstdint>
#include <cstddef>

#define NPTS 4096
#define BATCH 4
#define C1 512
#define H1 864
#define H2 1728
#define KNN 5
#define NCAND 8
#define KP1 512
#define KP2 896
#define J1P 1792
#define J2P 3456

#define BM 128
#define BN 128
#define BKH 32
#define ROWH 40
#define NSTAGE 5
#define NCHK 32          // partial chunks per row (4096/128)
#define DTS 129          // staged D tile row stride (floats)

// ---------------- scratch (device globals) ----------------------------------
__device__ __align__(16) float g_PQ[(size_t)BATCH * NPTS * J2P];
__device__ __align__(16) float g_X1[(size_t)BATCH * NPTS * H1];
__device__ __align__(16) __nv_bfloat16 g_XA[(size_t)3 * BATCH * NPTS * KP2];
__device__ __align__(16) __nv_bfloat16 g_WB[(size_t)3 * J2P * KP2];
__device__ float g_sq[BATCH * NPTS];
__device__ int   g_idx[BATCH * NPTS * KNN];
__device__ int   g_cand[BATCH * NPTS * NCAND];
__device__ __align__(16) float g_pv[(size_t)BATCH * NPTS * NCHK * NCAND];
__device__ __align__(16) int   g_pi[(size_t)BATCH * NPTS * NCHK * NCAND];

// ---------------- helpers ----------------------------------------------------
__device__ __forceinline__ uint32_t smem_u32(const void* p) {
    uint32_t a;
    asm("{ .reg .u64 t; cvta.to.shared.u64 t, %1; cvt.u32.u64 %0, t; }" : "=r"(a) : "l"(p));
    return a;
}
__device__ __forceinline__ void cp16(uint32_t s, const void* g) {
    asm volatile("cp.async.cg.shared.global [%0], [%1], 16;" :: "r"(s), "l"(g));
}
__device__ __forceinline__ void cp_commit() { asm volatile("cp.async.commit_group;" ::: "memory"); }
__device__ __forceinline__ void cp_wait3()  { asm volatile("cp.async.wait_group 3;" ::: "memory"); }
__device__ __forceinline__ void ldsm4(uint32_t* r, uint32_t a) {
    asm volatile("ldmatrix.sync.aligned.m8n8.x4.shared.b16 {%0,%1,%2,%3}, [%4];"
        : "=r"(r[0]), "=r"(r[1]), "=r"(r[2]), "=r"(r[3]) : "r"(a));
}
__device__ __forceinline__ void mma16816(float* c, const uint32_t* a, const uint32_t* b) {
    asm volatile(
        "mma.sync.aligned.m16n8k16.row.col.f32.bf16.bf16.f32 "
        "{%0,%1,%2,%3}, {%4,%5,%6,%7}, {%8,%9}, {%0,%1,%2,%3};"
        : "+f"(c[0]), "+f"(c[1]), "+f"(c[2]), "+f"(c[3])
        : "r"(a[0]), "r"(a[1]), "r"(a[2]), "r"(a[3]), "r"(b[0]), "r"(b[1]));
}
#define NEGINF (-__int_as_float(0x7f800000))

// ---------------- small kernels ---------------------------------------------
__global__ void rowsq_kernel(const float* __restrict__ X, float* __restrict__ sq, int Cdim) {
    int b = blockIdx.y, n = blockIdx.x;
    const float* x = X + ((size_t)b * NPTS + n) * Cdim;
    double s = 0.0;
    for (int c = threadIdx.x; c < Cdim; c += 128) { float v = x[c]; s += (double)(v * v); }
    for (int off = 16; off; off >>= 1) s += __shfl_down_sync(0xffffffffu, s, off);
    __shared__ double red[4];
    if ((threadIdx.x & 31) == 0) red[threadIdx.x >> 5] = s;
    __syncthreads();
    if (threadIdx.x == 0) sq[b * NPTS + n] = (float)(red[0] + red[1] + red[2] + red[3]);
}

__global__ void split3x_kernel(const float* __restrict__ X, __nv_bfloat16* __restrict__ P,
                               int Cin, int Kp, size_t planeStride) {
    size_t total = (size_t)BATCH * NPTS * Kp;
    for (size_t t = (size_t)blockIdx.x * blockDim.x + threadIdx.x; t < total;
         t += (size_t)gridDim.x * blockDim.x) {
        size_t bn = t / Kp; int c = (int)(t - bn * Kp);
        float x = (c < Cin) ? X[bn * Cin + c] : 0.f;
        __nv_bfloat16 h0 = __float2bfloat16(x);
        float r1 = x - __bfloat162float(h0);
        __nv_bfloat16 h1 = __float2bfloat16(r1);
        float r2 = r1 - __bfloat162float(h1);
        P[t] = h0; P[planeStride + t] = h1; P[2 * planeStride + t] = __float2bfloat16(r2);
    }
}

__global__ void splitW_kernel(const float* __restrict__ W, __nv_bfloat16* __restrict__ P,
                              int Cin, int OUT, int Kp, size_t planeStride) {
    size_t total = (size_t)2 * OUT * Kp;
    for (size_t t = (size_t)blockIdx.x * blockDim.x + threadIdx.x; t < total;
         t += (size_t)gridDim.x * blockDim.x) {
        size_t j = t / Kp; int c = (int)(t - j * Kp);
        float w = 0.f;
        if (c < Cin) {
            if ((int)j < OUT) w = W[j * (2 * Cin) + c];
            else { size_t o = j - OUT; w = __fadd_rn(W[o * (2 * Cin) + Cin + c], -W[o * (2 * Cin) + c]); }
        }
        __nv_bfloat16 h0 = __float2bfloat16(w);
        float r1 = w - __bfloat162float(h0);
        __nv_bfloat16 h1 = __float2bfloat16(r1);
        float r2 = r1 - __bfloat162float(h1);
        P[t] = h0; P[planeStride + t] = h1; P[2 * planeStride + t] = __float2bfloat16(r2);
    }
}

// ---------------- HMMA GEMM (128x128, ldmatrix, 5-stage pipeline) ------------
// mode 0: distance tile -> fused per-row/per-col top-8 partials (no D matrix)
// mode 1: PQ = X@W^T (float out)
struct TermList { int n; int pa[3]; int pb[3]; };

__global__ __launch_bounds__(256, 2) void hmma_gemm_kernel(
    const __nv_bfloat16* __restrict__ A0, const __nv_bfloat16* __restrict__ B0,
    size_t aPlane, size_t bPlane, size_t aBatch, size_t bBatch,
    int Kp, TermList tl, int mode,
    const float* __restrict__ sq, float* __restrict__ Out, int JS,
    float* __restrict__ pv, int* __restrict__ pi) {
    extern __shared__ __align__(16) char dyn[];
    __nv_bfloat16* smA = (__nv_bfloat16*)dyn;                               // NSTAGE x 128 x 40
    __nv_bfloat16* smB = (__nv_bfloat16*)(dyn + NSTAGE * BM * ROWH * 2);

    int tid = threadIdx.x;
    int bb = blockIdx.z;
    int br = blockIdx.y, bc = blockIdx.x;
    if (mode == 0 && bc > br) return;
    int rowA = br * BM, rowB = bc * BN;

    const __nv_bfloat16* Aptr[3];
    const __nv_bfloat16* Bptr[3];
#pragma unroll
    for (int t = 0; t < 3; t++) {
        int tt = (t < tl.n) ? t : 0;
        Aptr[t] = A0 + (size_t)tl.pa[tt] * aPlane + (size_t)bb * aBatch + (size_t)rowA * Kp;
        Bptr[t] = B0 + (size_t)tl.pb[tt] * bPlane + (size_t)bb * bBatch + (size_t)rowB * Kp;
    }

    int r0 = tid >> 2, c0 = (tid & 3) * 8;
    int r1 = (tid + 256) >> 2, c1 = ((tid + 256) & 3) * 8;

    int lane = tid & 31, wid = tid >> 5;
    int g = lane >> 2, t4 = lane & 3;
    int q = lane >> 3, lr = lane & 7;
    int wm = (wid >> 2) * 64, wn = (wid & 3) * 32;
    int rowOffA = (q & 1) * 8 + lr, colOffA = (q >> 1) * 8;
    int rowOffB = (q >> 1) * 8 + lr, colOffB = (q & 1) * 8;

    int chPer = Kp >> 5;
    int nch = tl.n * chPer;

    uint32_t sAu = smem_u32(smA), sBu = smem_u32(smB);

#pragma unroll
    for (int s = 0; s < NSTAGE - 1; s++) {
        int tt = s / chPer, kc = s - tt * chPer;
        int ko = kc * BKH;
        uint32_t a = sAu + s * BM * ROWH * 2;
        uint32_t b = sBu + s * BN * ROWH * 2;
        cp16(a + (r0 * ROWH + c0) * 2, Aptr[tt] + (size_t)r0 * Kp + ko + c0);
        cp16(a + (r1 * ROWH + c1) * 2, Aptr[tt] + (size_t)r1 * Kp + ko + c1);
        cp16(b + (r0 * ROWH + c0) * 2, Bptr[tt] + (size_t)r0 * Kp + ko + c0);
        cp16(b + (r1 * ROWH + c1) * 2, Bptr[tt] + (size_t)r1 * Kp + ko + c1);
        cp_commit();
    }

    float acc[4][4][4];
#pragma unroll
    for (int mi = 0; mi < 4; mi++)
#pragma unroll
        for (int ni = 0; ni < 4; ni++)
#pragma unroll
            for (int p = 0; p < 4; p++) acc[mi][ni][p] = 0.f;

    int stage = 0;
    for (int ci = 0; ci < nch; ci++) {
        cp_wait3();
        __syncthreads();

        uint32_t aS = sAu + stage * BM * ROWH * 2;
        uint32_t bS = sBu + stage * BN * ROWH * 2;
#pragma unroll
        for (int kk = 0; kk < 2; kk++) {
            int k0 = kk * 16;
            uint32_t af[4][4], bfr[2][4];
#pragma unroll
            for (int mi = 0; mi < 4; mi++)
                ldsm4(af[mi], aS + ((wm + mi * 16 + rowOffA) * ROWH + k0 + colOffA) * 2);
#pragma unroll
            for (int np = 0; np < 2; np++)
                ldsm4(bfr[np], bS + ((wn + np * 16 + rowOffB) * ROWH + k0 + colOffB) * 2);
#pragma unroll
            for (int mi = 0; mi < 4; mi++)
#pragma unroll
                for (int ni = 0; ni < 4; ni++)
                    mma16816(acc[mi][ni], af[mi], &bfr[ni >> 1][(ni & 1) * 2]);
        }

        int nb = ci + NSTAGE - 1;
        if (nb < nch) {
            int tt = nb / chPer, kc = nb - tt * chPer;
            int ko = kc * BKH;
            int st2 = nb % NSTAGE;
            uint32_t a = sAu + st2 * BM * ROWH * 2;
            uint32_t b = sBu + st2 * BN * ROWH * 2;
            cp16(a + (r0 * ROWH + c0) * 2, Aptr[tt] + (size_t)r0 * Kp + ko + c0);
            cp16(a + (r1 * ROWH + c1) * 2, Aptr[tt] + (size_t)r1 * Kp + ko + c1);
            cp16(b + (r0 * ROWH + c0) * 2, Bptr[tt] + (size_t)r0 * Kp + ko + c0);
            cp16(b + (r1 * ROWH + c1) * 2, Bptr[tt] + (size_t)r1 * Kp + ko + c1);
        }
        cp_commit();
        stage = (stage + 1 == NSTAGE) ? 0 : stage + 1;
    }

    if (mode == 0) {
        // ---- fused selection epilogue ----
        const float* sqb = sq + bb * NPTS;
        __syncthreads();   // pipeline smem is dead (all pending cp groups are empty)
        float* Dt  = (float*)dyn;                         // 128 x 129 floats
        float* Pub = (float*)(dyn + BM * DTS * 4);        // 128 x 8
        int*  PubI = (int*)(dyn + BM * DTS * 4 + 4096);   // 128 x 8
#pragma unroll
        for (int mi = 0; mi < 4; mi++) {
            int rr0 = wm + mi * 16 + g, rr1 = rr0 + 8;
            float sn0 = sqb[rowA + rr0], sn1 = sqb[rowA + rr1];
#pragma unroll
            for (int ni = 0; ni < 4; ni++) {
                int cc0 = wn + ni * 8 + 2 * t4;
#pragma unroll
                for (int h = 0; h < 2; h++) {
                    int c = cc0 + h;
                    float smv = sqb[rowB + c];
                    Dt[rr0 * DTS + c] = -__fadd_rn(__fadd_rn(sn0, smv), -__fmul_rn(2.0f, acc[mi][ni][0 + h]));
                    Dt[rr1 * DTS + c] = -__fadd_rn(__fadd_rn(sn1, smv), -__fmul_rn(2.0f, acc[mi][ni][2 + h]));
                }
            }
        }
        __syncthreads();

        int rr = tid >> 1, h2 = tid & 1;
        // ---- row scan: top-8 over this tile's 128 columns ----
        {
            float tv[NCAND]; int ti8[NCAND];
#pragma unroll
            for (int j = 0; j < NCAND; j++) { tv[j] = NEGINF; ti8[j] = 0x7fffffff; }
            const float* dr = Dt + rr * DTS + h2 * 64;
            int ibase = rowB + h2 * 64;
#pragma unroll 4
            for (int j = 0; j < 64; j++) {
                float v = dr[j];
                if (v > tv[NCAND - 1]) {
                    int p = NCAND - 1;
                    while (p > 0 && v > tv[p - 1]) { tv[p] = tv[p - 1]; ti8[p] = ti8[p - 1]; p--; }
                    tv[p] = v; ti8[p] = ibase + j;
                }
            }
            if (h2 == 1) {
#pragma unroll
                for (int j = 0; j < NCAND; j++) { Pub[rr * 8 + j] = tv[j]; PubI[rr * 8 + j] = ti8[j]; }
            }
            __syncthreads();
            if (h2 == 0) {
                const float* sv = Pub + rr * 8;
                const int* si = PubI + rr * 8;
                size_t ob = (((size_t)bb * NPTS + rowA + rr) * NCHK + bc) * NCAND;
                int ia = 0, ib2 = 0;
#pragma unroll
                for (int p = 0; p < NCAND; p++) {
                    bool ta = (tv[ia] > sv[ib2]) || (tv[ia] == sv[ib2] && ti8[ia] < si[ib2]);
                    if (ta) { pv[ob + p] = tv[ia]; pi[ob + p] = ti8[ia]; ia++; }
                    else    { pv[ob + p] = sv[ib2]; pi[ob + p] = si[ib2]; ib2++; }
                }
            }
        }
        // ---- column scan: covers the mirrored strip (skip on diagonal) ----
        if (br != bc) {
            __syncthreads();
            float tv[NCAND]; int ti8[NCAND];
#pragma unroll
            for (int j = 0; j < NCAND; j++) { tv[j] = NEGINF; ti8[j] = 0x7fffffff; }
            int jb = h2 * 64;
#pragma unroll 4
            for (int j = 0; j < 64; j++) {
                float v = Dt[(jb + j) * DTS + rr];
                if (v > tv[NCAND - 1]) {
                    int p = NCAND - 1;
                    while (p > 0 && v > tv[p - 1]) { tv[p] = tv[p - 1]; ti8[p] = ti8[p - 1]; p--; }
                    tv[p] = v; ti8[p] = rowA + jb + j;
                }
            }
            if (h2 == 1) {
#pragma unroll
                for (int j = 0; j < NCAND; j++) { Pub[rr * 8 + j] = tv[j]; PubI[rr * 8 + j] = ti8[j]; }
            }
            __syncthreads();
            if (h2 == 0) {
                const float* sv = Pub + rr * 8;
                const int* si = PubI + rr * 8;
                size_t ob = (((size_t)bb * NPTS + rowB + rr) * NCHK + br) * NCAND;
                int ia = 0, ib2 = 0;
#pragma unroll
                for (int p = 0; p < NCAND; p++) {
                    bool ta = (tv[ia] > sv[ib2]) || (tv[ia] == sv[ib2] && ti8[ia] < si[ib2]);
                    if (ta) { pv[ob + p] = tv[ia]; pi[ob + p] = ti8[ia]; ia++; }
                    else    { pv[ob + p] = sv[ib2]; pi[ob + p] = si[ib2]; ib2++; }
                }
            }
        }
    } else {
        float* Ob = Out + (size_t)bb * NPTS * (size_t)JS;
#pragma unroll
        for (int mi = 0; mi < 4; mi++) {
            int n0 = rowA + wm + mi * 16 + g, n1 = n0 + 8;
#pragma unroll
            for (int ni = 0; ni < 4; ni++) {
                int j0 = rowB + wn + ni * 8 + 2 * t4;
                *(float2*)&Ob[(size_t)n0 * JS + j0] = make_float2(acc[mi][ni][0], acc[mi][ni][1]);
                *(float2*)&Ob[(size_t)n1 * JS + j0] = make_float2(acc[mi][ni][2], acc[mi][ni][3]);
            }
        }
    }
}

// ---------------- merge 32 sorted runs of 8 -> global top-8 ------------------
__global__ void topkm_kernel(const float* __restrict__ pv, const int* __restrict__ pi,
                             int* __restrict__ cand) {
    int b = blockIdx.y, n = blockIdx.x, lane = threadIdx.x;   // 32 threads
    size_t base = ((size_t)b * NPTS + n) * (NCHK * NCAND) + (size_t)lane * NCAND;
    float v[NCAND]; int id[NCAND];
    float4 f0 = *(const float4*)(pv + base), f1 = *(const float4*)(pv + base + 4);
    int4  i0 = *(const int4*)(pi + base),  i1 = *(const int4*)(pi + base + 4);
    v[0] = f0.x; v[1] = f0.y; v[2] = f0.z; v[3] = f0.w;
    v[4] = f1.x; v[5] = f1.y; v[6] = f1.z; v[7] = f1.w;
    id[0] = i0.x; id[1] = i0.y; id[2] = i0.z; id[3] = i0.w;
    id[4] = i1.x; id[5] = i1.y; id[6] = i1.z; id[7] = i1.w;
    int head = 0;
    int* co = cand + ((size_t)b * NPTS + n) * NCAND;
    for (int p = 0; p < NCAND; p++) {
        float bv = (head < NCAND) ? v[head] : NEGINF;
        int bi = (head < NCAND) ? id[head] : 0x7fffffff;
        int bl = lane;
        for (int off = 16; off; off >>= 1) {
            float ov = __shfl_down_sync(0xffffffffu, bv, off);
            int oi = __shfl_down_sync(0xffffffffu, bi, off);
            int ol = __shfl_down_sync(0xffffffffu, bl, off);
            if (ov > bv || (ov == bv && oi < bi)) { bv = ov; bi = oi; bl = ol; }
        }
        bi = __shfl_sync(0xffffffffu, bi, 0);
        bl = __shfl_sync(0xffffffffu, bl, 0);
        if (lane == 0) co[p] = bi;
        if (lane == bl) head++;
    }
}

// ---------------- exact rescore: warp per candidate --------------------------
__global__ __launch_bounds__(256) void rescore_kernel(
    const float* __restrict__ X, const float* __restrict__ sq,
    const int* __restrict__ cand, int* __restrict__ idx, int Cdim) {
    int b = blockIdx.y, n = blockIdx.x, tid = threadIdx.x;
    int lane = tid & 31, wid = tid >> 5;
    __shared__ float xn[896];
    __shared__ float vals[NCAND];
    __shared__ int   vm[NCAND];
    const float* xrow = X + ((size_t)b * NPTS + n) * Cdim;
    for (int c = tid; c < Cdim; c += 256) xn[c] = xrow[c];
    __syncthreads();
    const float* sqb = sq + b * NPTS;
    float sn = sqb[n];
    int m = cand[((size_t)b * NPTS + n) * NCAND + wid];
    const float* xm = X + ((size_t)b * NPTS + m) * Cdim;
    double s = 0.0;
    for (int c = lane; c < Cdim; c += 32) s += (double)xn[c] * (double)xm[c];
    for (int off = 16; off; off >>= 1) s += __shfl_down_sync(0xffffffffu, s, off);
    if (lane == 0) {
        float Gf = (float)s;
        float t1 = __fadd_rn(sn, sqb[m]);
        vals[wid] = -__fadd_rn(t1, -__fmul_rn(2.0f, Gf));
        vm[wid] = m;
    }
    __syncthreads();
    if (tid == 0) {
        bool used[NCAND] = {};
        for (int p = 0; p < KNN; p++) {
            float bv = NEGINF; int bi = 0x7fffffff, bj = -1;
            for (int j = 0; j < NCAND; j++) {
                if (used[j]) continue;
                if (vals[j] > bv || (vals[j] == bv && vm[j] < bi)) { bv = vals[j]; bi = vm[j]; bj = j; }
            }
            used[bj] = true;
            idx[((size_t)b * NPTS + n) * KNN + p] = bi;
        }
    }
}

// ---------------- gather + max over k + BN + LeakyReLU (float4) --------------
__global__ void gathermax_kernel(const float* __restrict__ PQ, const int* __restrict__ idx,
                                 const float* __restrict__ gamma, const float* __restrict__ beta,
                                 const float* __restrict__ mean, const float* __restrict__ var,
                                 float* __restrict__ out, int OUT, int JS) {
    int b = blockIdx.y, n = blockIdx.x;
    __shared__ int nb[KNN];
    if (threadIdx.x < KNN) nb[threadIdx.x] = idx[((size_t)b * NPTS + n) * KNN + threadIdx.x];
    __syncthreads();
    const float* base = PQ + (size_t)b * NPTS * JS;
    const float4* p0 = (const float4*)(base + (size_t)nb[0] * JS);
    const float4* p1 = (const float4*)(base + (size_t)nb[1] * JS);
    const float4* p2 = (const float4*)(base + (size_t)nb[2] * JS);
    const float4* p3 = (const float4*)(base + (size_t)nb[3] * JS);
    const float4* p4 = (const float4*)(base + (size_t)nb[4] * JS);
    const float4* qv = (const float4*)(base + (size_t)n * JS + OUT);
    float4* orow = (float4*)(out + ((size_t)b * NPTS + n) * OUT);
    int n4 = OUT / 4;
    for (int o = threadIdx.x; o < n4; o += blockDim.x) {
        float4 a = p0[o], v1 = p1[o], v2 = p2[o], v3 = p3[o], v4 = p4[o], qq = qv[o];
        float4 gg = ((const float4*)gamma)[o], be = ((const float4*)beta)[o];
        float4 me = ((const float4*)mean)[o], va = ((const float4*)var)[o];
        float mx[4] = {
            fmaxf(fmaxf(fmaxf(a.x, v1.x), fmaxf(v2.x, v3.x)), v4.x),
            fmaxf(fmaxf(fmaxf(a.y, v1.y), fmaxf(v2.y, v3.y)), v4.y),
            fmaxf(fmaxf(fmaxf(a.z, v1.z), fmaxf(v2.z, v3.z)), v4.z),
            fmaxf(fmaxf(fmaxf(a.w, v1.w), fmaxf(v2.w, v3.w)), v4.w) };
        float qa[4] = { qq.x, qq.y, qq.z, qq.w };
        float ga[4] = { gg.x, gg.y, gg.z, gg.w }, ba[4] = { be.x, be.y, be.z, be.w };
        float ma[4] = { me.x, me.y, me.z, me.w }, vva[4] = { va.x, va.y, va.z, va.w };
        float4 res;
        float* rp = (float*)&res;
#pragma unroll
        for (int u = 0; u < 4; u++) {
            double h = (double)mx[u] + (double)qa[u];
            double sc = (double)ga[u] * rsqrt((double)vva[u] + 1e-5);
            double v = (h - (double)ma[u]) * sc + (double)ba[u];
            float vf = (float)v;
            rp[u] = (vf >= 0.f) ? vf : 0.2f * vf;
        }
        orow[o] = res;
    }
}

// ---------------- launcher ---------------------------------------------------
extern "C" void kernel_launch(void* const* d_in, const int* in_sizes, int n_in,
                              void* d_out, int out_size) {
    const float* X0 = (const float*)d_in[0];
    const float* W1 = (const float*)d_in[1];
    const float* g1 = (const float*)d_in[2];
    const float* b1 = (const float*)d_in[3];
    const float* m1 = (const float*)d_in[4];
    const float* v1 = (const float*)d_in[5];
    const float* W2 = (const float*)d_in[6];
    const float* g2 = (const float*)d_in[7];
    const float* b2 = (const float*)d_in[8];
    const float* m2 = (const float*)d_in[9];
    const float* v2 = (const float*)d_in[10];
    float* out = (float*)d_out;

    float *pPQ, *pX1, *pSq, *pPv;
    __nv_bfloat16 *pXA, *pWB;
    int *pIdx, *pCand, *pPi;
    cudaGetSymbolAddress((void**)&pPQ, g_PQ);
    cudaGetSymbolAddress((void**)&pX1, g_X1);
    cudaGetSymbolAddress((void**)&pXA, g_XA);
    cudaGetSymbolAddress((void**)&pWB, g_WB);
    cudaGetSymbolAddress((void**)&pSq, g_sq);
    cudaGetSymbolAddress((void**)&pIdx, g_idx);
    cudaGetSymbolAddress((void**)&pCand, g_cand);
    cudaGetSymbolAddress((void**)&pPv, g_pv);
    cudaGetSymbolAddress((void**)&pPi, g_pi);

    const int DSM = NSTAGE * (BM + BN) * ROWH * 2;   // 102400 (>= selection scratch 74 KB)
    cudaFuncSetAttribute(hmma_gemm_kernel, cudaFuncAttributeMaxDynamicSharedMemorySize, DSM);

    TermList T1; T1.n = 1;
    T1.pa[0] = 0; T1.pb[0] = 0; T1.pa[1] = T1.pa[2] = 0; T1.pb[1] = T1.pb[2] = 0;
    TermList T3; T3.n = 3;
    T3.pa[0] = 0; T3.pb[0] = 0;
    T3.pa[1] = 0; T3.pb[1] = 1;
    T3.pa[2] = 1; T3.pb[2] = 0;

    size_t aPlane1 = (size_t)BATCH * NPTS * KP1;
    size_t aPlane2 = (size_t)BATCH * NPTS * KP2;
    size_t wPlane  = (size_t)J2P * KP2;

    // ---- Layer 1 (Cin=512, OUT=864, JS=1792) ----
    rowsq_kernel<<<dim3(NPTS, BATCH), 128>>>(X0, pSq, C1);
    split3x_kernel<<<4096, 256>>>(X0, pXA, C1, KP1, aPlane1);
    splitW_kernel<<<2048, 256>>>(W1, pWB, C1, H1, KP1, wPlane);
    hmma_gemm_kernel<<<dim3(32, 32, BATCH), 256, DSM>>>(
        pXA, pXA, aPlane1, aPlane1, (size_t)NPTS * KP1, (size_t)NPTS * KP1,
        KP1, T1, 0, pSq, nullptr, NPTS, pPv, pPi);
    topkm_kernel<<<dim3(NPTS, BATCH), 32>>>(pPv, pPi, pCand);
    rescore_kernel<<<dim3(NPTS, BATCH), 256>>>(X0, pSq, pCand, pIdx, C1);
    hmma_gemm_kernel<<<dim3(J1P / BN, 32, BATCH), 256, DSM>>>(
        pXA, pWB, aPlane1, wPlane, (size_t)NPTS * KP1, 0,
        KP1, T3, 1, pSq, pPQ, J1P, pPv, pPi);
    gathermax_kernel<<<dim3(NPTS, BATCH), 256>>>(pPQ, pIdx, g1, b1, m1, v1, pX1, H1, J1P);

    // ---- Layer 2 (Cin=864 pad 896, OUT=1728, JS=3456) ----
    rowsq_kernel<<<dim3(NPTS, BATCH), 128>>>(pX1, pSq, H1);
    split3x_kernel<<<4096, 256>>>(pX1, pXA, H1, KP2, aPlane2);
    splitW_kernel<<<4096, 256>>>(W2, pWB, H1, H2, KP2, wPlane);
    hmma_gemm_kernel<<<dim3(32, 32, BATCH), 256, DSM>>>(
        pXA, pXA, aPlane2, aPlane2, (size_t)NPTS * KP2, (size_t)NPTS * KP2,
        KP2, T1, 0, pSq, nullptr, NPTS, pPv, pPi);
    topkm_kernel<<<dim3(NPTS, BATCH), 32>>>(pPv, pPi, pCand);
    rescore_kernel<<<dim3(NPTS, BATCH), 256>>>(pX1, pSq, pCand, pIdx, H1);
    hmma_gemm_kernel<<<dim3(J2P / BN, 32, BATCH), 256, DSM>>>(
        pXA, pWB, aPlane2, wPlane, (size_t)NPTS * KP2, 0,
        KP2, T3, 1, pSq, pPQ, J2P, pPv, pPi);
    gathermax_kernel<<<dim3(NPTS, BATCH), 256>>>(pPQ, pIdx, g2, b2, m2, v2, out, H2, J2P);
}

// round 10
// speedup vs baseline: 1.3283x; 1.3283x over previous
#include <cuda_runtime.h>
#include <cuda_bf16.h>
#include <cstdint>
#include <cstddef>

#define NPTS 4096
#define BATCH 4
#define C1 512
#define H1 864
#define H2 1728
#define KNN 5
#define NCAND 8
#define KP1 512
#define KP2 896
#define J1P 1792
#define J2P 3456

#define BM 128
#define BN 128
#define BKH 32
#define ROWH 40
#define NSTAGE 5
#define NCHK 4          // topk phase-A chunks per row (4096/1024)
#define TILEB (BM * ROWH * 2)     // 10240 bytes per 128x32h tile

// ---------------- scratch (device globals) ----------------------------------
__device__ __align__(16) float g_D[(size_t)BATCH * NPTS * NPTS];
__device__ __align__(16) float g_PQ[(size_t)BATCH * NPTS * J2P];
__device__ __align__(16) float g_X1[(size_t)BATCH * NPTS * H1];
__device__ __align__(16) __nv_bfloat16 g_XA[(size_t)3 * BATCH * NPTS * KP2];
__device__ __align__(16) __nv_bfloat16 g_WB[(size_t)3 * J2P * KP2];
__device__ float g_sq[BATCH * NPTS];
__device__ int   g_idx[BATCH * NPTS * KNN];
__device__ int   g_cand[BATCH * NPTS * NCAND];
__device__ float g_pv[(size_t)BATCH * NPTS * NCHK * NCAND];
__device__ int   g_pi[(size_t)BATCH * NPTS * NCHK * NCAND];

// ---------------- helpers ----------------------------------------------------
__device__ __forceinline__ uint32_t smem_u32(const void* p) {
    uint32_t a;
    asm("{ .reg .u64 t; cvta.to.shared.u64 t, %1; cvt.u32.u64 %0, t; }" : "=r"(a) : "l"(p));
    return a;
}
__device__ __forceinline__ void cp16(uint32_t s, const void* g) {
    asm volatile("cp.async.cg.shared.global [%0], [%1], 16;" :: "r"(s), "l"(g));
}
__device__ __forceinline__ void cp_commit() { asm volatile("cp.async.commit_group;" ::: "memory"); }
__device__ __forceinline__ void cp_wait3()  { asm volatile("cp.async.wait_group 3;" ::: "memory"); }
__device__ __forceinline__ void cp_wait1()  { asm volatile("cp.async.wait_group 1;" ::: "memory"); }
__device__ __forceinline__ void cp_wait0()  { asm volatile("cp.async.wait_group 0;" ::: "memory"); }
__device__ __forceinline__ void ldsm4(uint32_t* r, uint32_t a) {
    asm volatile("ldmatrix.sync.aligned.m8n8.x4.shared.b16 {%0,%1,%2,%3}, [%4];"
        : "=r"(r[0]), "=r"(r[1]), "=r"(r[2]), "=r"(r[3]) : "r"(a));
}
__device__ __forceinline__ void mma16816(float* c, const uint32_t* a, const uint32_t* b) {
    asm volatile(
        "mma.sync.aligned.m16n8k16.row.col.f32.bf16.bf16.f32 "
        "{%0,%1,%2,%3}, {%4,%5,%6,%7}, {%8,%9}, {%0,%1,%2,%3};"
        : "+f"(c[0]), "+f"(c[1]), "+f"(c[2]), "+f"(c[3])
        : "r"(a[0]), "r"(a[1]), "r"(a[2]), "r"(a[3]), "r"(b[0]), "r"(b[1]));
}
#define NEGINF (-__int_as_float(0x7f800000))

// ---------------- small kernels ---------------------------------------------
__global__ void rowsq_kernel(const float* __restrict__ X, float* __restrict__ sq, int Cdim) {
    int b = blockIdx.y, n = blockIdx.x;
    const float* x = X + ((size_t)b * NPTS + n) * Cdim;
    double s = 0.0;
    for (int c = threadIdx.x; c < Cdim; c += 128) { float v = x[c]; s += (double)(v * v); }
    for (int off = 16; off; off >>= 1) s += __shfl_down_sync(0xffffffffu, s, off);
    __shared__ double red[4];
    if ((threadIdx.x & 31) == 0) red[threadIdx.x >> 5] = s;
    __syncthreads();
    if (threadIdx.x == 0) sq[b * NPTS + n] = (float)(red[0] + red[1] + red[2] + red[3]);
}

__global__ void split3x_kernel(const float* __restrict__ X, __nv_bfloat16* __restrict__ P,
                               int Cin, int Kp, size_t planeStride) {
    size_t total = (size_t)BATCH * NPTS * Kp;
    for (size_t t = (size_t)blockIdx.x * blockDim.x + threadIdx.x; t < total;
         t += (size_t)gridDim.x * blockDim.x) {
        size_t bn = t / Kp; int c = (int)(t - bn * Kp);
        float x = (c < Cin) ? X[bn * Cin + c] : 0.f;
        __nv_bfloat16 h0 = __float2bfloat16(x);
        float r1 = x - __bfloat162float(h0);
        __nv_bfloat16 h1 = __float2bfloat16(r1);
        float r2 = r1 - __bfloat162float(h1);
        P[t] = h0; P[planeStride + t] = h1; P[2 * planeStride + t] = __float2bfloat16(r2);
    }
}

__global__ void splitW_kernel(const float* __restrict__ W, __nv_bfloat16* __restrict__ P,
                              int Cin, int OUT, int Kp, size_t planeStride) {
    size_t total = (size_t)2 * OUT * Kp;
    for (size_t t = (size_t)blockIdx.x * blockDim.x + threadIdx.x; t < total;
         t += (size_t)gridDim.x * blockDim.x) {
        size_t j = t / Kp; int c = (int)(t - j * Kp);
        float w = 0.f;
        if (c < Cin) {
            if ((int)j < OUT) w = W[j * (2 * Cin) + c];
            else { size_t o = j - OUT; w = __fadd_rn(W[o * (2 * Cin) + Cin + c], -W[o * (2 * Cin) + c]); }
        }
        __nv_bfloat16 h0 = __float2bfloat16(w);
        float r1 = w - __bfloat162float(h0);
        __nv_bfloat16 h1 = __float2bfloat16(r1);
        float r2 = r1 - __bfloat162float(h1);
        P[t] = h0; P[planeStride + t] = h1; P[2 * planeStride + t] = __float2bfloat16(r2);
    }
}

// ---------------- distance GEMM (128x128, ldmatrix, 5-stage) -----------------
__global__ __launch_bounds__(256, 2) void dist_gemm_kernel(
    const __nv_bfloat16* __restrict__ A0, size_t aBatch,
    int Kp, const float* __restrict__ sq, float* __restrict__ Out) {
    extern __shared__ __align__(16) char dyn[];
    __nv_bfloat16* smA = (__nv_bfloat16*)dyn;
    __nv_bfloat16* smB = (__nv_bfloat16*)(dyn + NSTAGE * TILEB);

    int tid = threadIdx.x;
    int bb = blockIdx.z;
    int br = blockIdx.y, bc = blockIdx.x;
    if (bc > br) return;
    int rowA = br * BM, rowB = bc * BN;

    const __nv_bfloat16* Ap = A0 + (size_t)bb * aBatch + (size_t)rowA * Kp;
    const __nv_bfloat16* Bp = A0 + (size_t)bb * aBatch + (size_t)rowB * Kp;

    int r0 = tid >> 2, c0 = (tid & 3) * 8;
    int r1 = (tid + 256) >> 2, c1 = ((tid + 256) & 3) * 8;

    int lane = tid & 31, wid = tid >> 5;
    int g = lane >> 2, t4 = lane & 3;
    int q = lane >> 3, lr = lane & 7;
    int wm = (wid >> 2) * 64, wn = (wid & 3) * 32;
    int rowOffA = (q & 1) * 8 + lr, colOffA = (q >> 1) * 8;
    int rowOffB = (q >> 1) * 8 + lr, colOffB = (q & 1) * 8;

    int nch = Kp >> 5;
    uint32_t sAu = smem_u32(smA), sBu = smem_u32(smB);

#pragma unroll
    for (int s = 0; s < NSTAGE - 1; s++) {
        int ko = s * BKH;
        uint32_t a = sAu + s * TILEB;
        uint32_t b = sBu + s * TILEB;
        cp16(a + (r0 * ROWH + c0) * 2, Ap + (size_t)r0 * Kp + ko + c0);
        cp16(a + (r1 * ROWH + c1) * 2, Ap + (size_t)r1 * Kp + ko + c1);
        cp16(b + (r0 * ROWH + c0) * 2, Bp + (size_t)r0 * Kp + ko + c0);
        cp16(b + (r1 * ROWH + c1) * 2, Bp + (size_t)r1 * Kp + ko + c1);
        cp_commit();
    }

    float acc[4][4][4];
#pragma unroll
    for (int mi = 0; mi < 4; mi++)
#pragma unroll
        for (int ni = 0; ni < 4; ni++)
#pragma unroll
            for (int p = 0; p < 4; p++) acc[mi][ni][p] = 0.f;

    int stage = 0;
    for (int ci = 0; ci < nch; ci++) {
        cp_wait3();
        __syncthreads();
        uint32_t aS = sAu + stage * TILEB;
        uint32_t bS = sBu + stage * TILEB;
#pragma unroll
        for (int kk = 0; kk < 2; kk++) {
            int k0 = kk * 16;
            uint32_t af[4][4], bfr[2][4];
#pragma unroll
            for (int mi = 0; mi < 4; mi++)
                ldsm4(af[mi], aS + ((wm + mi * 16 + rowOffA) * ROWH + k0 + colOffA) * 2);
#pragma unroll
            for (int np = 0; np < 2; np++)
                ldsm4(bfr[np], bS + ((wn + np * 16 + rowOffB) * ROWH + k0 + colOffB) * 2);
#pragma unroll
            for (int mi = 0; mi < 4; mi++)
#pragma unroll
                for (int ni = 0; ni < 4; ni++)
                    mma16816(acc[mi][ni], af[mi], &bfr[ni >> 1][(ni & 1) * 2]);
        }
        int nb = ci + NSTAGE - 1;
        if (nb < nch) {
            int ko = nb * BKH;
            int st2 = nb % NSTAGE;
            uint32_t a = sAu + st2 * TILEB;
            uint32_t b = sBu + st2 * TILEB;
            cp16(a + (r0 * ROWH + c0) * 2, Ap + (size_t)r0 * Kp + ko + c0);
            cp16(a + (r1 * ROWH + c1) * 2, Ap + (size_t)r1 * Kp + ko + c1);
            cp16(b + (r0 * ROWH + c0) * 2, Bp + (size_t)r0 * Kp + ko + c0);
            cp16(b + (r1 * ROWH + c1) * 2, Bp + (size_t)r1 * Kp + ko + c1);
        }
        cp_commit();
        stage = (stage + 1 == NSTAGE) ? 0 : stage + 1;
    }

    const float* sqb = sq + bb * NPTS;
    float* Db = Out + (size_t)bb * NPTS * NPTS;
    bool mirror = (br != bc);
#pragma unroll
    for (int mi = 0; mi < 4; mi++) {
        int n0 = rowA + wm + mi * 16 + g;
        int n1 = n0 + 8;
        float sn0 = sqb[n0], sn1 = sqb[n1];
#pragma unroll
        for (int ni = 0; ni < 4; ni++) {
            int m0 = rowB + wn + ni * 8 + 2 * t4;
#pragma unroll
            for (int h = 0; h < 2; h++) {
                int m = m0 + h;
                float sm_ = sqb[m];
                float v0 = -__fadd_rn(__fadd_rn(sn0, sm_), -__fmul_rn(2.0f, acc[mi][ni][0 + h]));
                float v1 = -__fadd_rn(__fadd_rn(sn1, sm_), -__fmul_rn(2.0f, acc[mi][ni][2 + h]));
                Db[(size_t)n0 * NPTS + m] = v0;
                Db[(size_t)n1 * NPTS + m] = v1;
                if (mirror) {
                    Db[(size_t)m * NPTS + n0] = v0;
                    Db[(size_t)m * NPTS + n1] = v1;
                }
            }
        }
    }
}

// ---------------- PQ GEMM: fused 3-term (A0,A1,B0,B1 per chunk) --------------
// acc = A0*B0 + A0*B1 + A1*B0, K chunks of 32, double-buffered.
__global__ __launch_bounds__(256, 2) void pq_gemm_kernel(
    const __nv_bfloat16* __restrict__ Ag, const __nv_bfloat16* __restrict__ Bg,
    size_t aPlane, size_t bPlane, size_t aBatch,
    int Kp, float* __restrict__ Out, int JS) {
    extern __shared__ __align__(16) char dyn[];
    // stage layout: A0 | A1 | B0 | B1, each 10240B; stage stride 40960B
    int tid = threadIdx.x;
    int bb = blockIdx.z;
    int rowA = blockIdx.y * BM, rowB = blockIdx.x * BN;

    const __nv_bfloat16* Ap0 = Ag + (size_t)bb * aBatch + (size_t)rowA * Kp;
    const __nv_bfloat16* Ap1 = Ap0 + aPlane;
    const __nv_bfloat16* Bp0 = Bg + (size_t)rowB * Kp;
    const __nv_bfloat16* Bp1 = Bp0 + bPlane;

    int r0 = tid >> 2, c0 = (tid & 3) * 8;
    int r1 = (tid + 256) >> 2, c1 = ((tid + 256) & 3) * 8;

    int lane = tid & 31, wid = tid >> 5;
    int g = lane >> 2, t4 = lane & 3;
    int q = lane >> 3, lr = lane & 7;
    int wm = (wid >> 2) * 64, wn = (wid & 3) * 32;
    int rowOffA = (q & 1) * 8 + lr, colOffA = (q >> 1) * 8;
    int rowOffB = (q >> 1) * 8 + lr, colOffB = (q & 1) * 8;

    int nch = Kp >> 5;
    uint32_t sm0 = smem_u32(dyn);

    // prefetch chunk 0 into stage 0
    {
        uint32_t st = sm0;
        cp16(st + 0 * TILEB + (r0 * ROWH + c0) * 2, Ap0 + (size_t)r0 * Kp + c0);
        cp16(st + 0 * TILEB + (r1 * ROWH + c1) * 2, Ap0 + (size_t)r1 * Kp + c1);
        cp16(st + 1 * TILEB + (r0 * ROWH + c0) * 2, Ap1 + (size_t)r0 * Kp + c0);
        cp16(st + 1 * TILEB + (r1 * ROWH + c1) * 2, Ap1 + (size_t)r1 * Kp + c1);
        cp16(st + 2 * TILEB + (r0 * ROWH + c0) * 2, Bp0 + (size_t)r0 * Kp + c0);
        cp16(st + 2 * TILEB + (r1 * ROWH + c1) * 2, Bp0 + (size_t)r1 * Kp + c1);
        cp16(st + 3 * TILEB + (r0 * ROWH + c0) * 2, Bp1 + (size_t)r0 * Kp + c0);
        cp16(st + 3 * TILEB + (r1 * ROWH + c1) * 2, Bp1 + (size_t)r1 * Kp + c1);
        cp_commit();
    }

    float acc[4][4][4];
#pragma unroll
    for (int mi = 0; mi < 4; mi++)
#pragma unroll
        for (int ni = 0; ni < 4; ni++)
#pragma unroll
            for (int p = 0; p < 4; p++) acc[mi][ni][p] = 0.f;

    for (int ci = 0; ci < nch; ci++) {
        int nb = ci + 1;
        if (nb < nch) {
            int ko = nb * BKH;
            uint32_t st = sm0 + (nb & 1) * 4 * TILEB;
            cp16(st + 0 * TILEB + (r0 * ROWH + c0) * 2, Ap0 + (size_t)r0 * Kp + ko + c0);
            cp16(st + 0 * TILEB + (r1 * ROWH + c1) * 2, Ap0 + (size_t)r1 * Kp + ko + c1);
            cp16(st + 1 * TILEB + (r0 * ROWH + c0) * 2, Ap1 + (size_t)r0 * Kp + ko + c0);
            cp16(st + 1 * TILEB + (r1 * ROWH + c1) * 2, Ap1 + (size_t)r1 * Kp + ko + c1);
            cp16(st + 2 * TILEB + (r0 * ROWH + c0) * 2, Bp0 + (size_t)r0 * Kp + ko + c0);
            cp16(st + 2 * TILEB + (r1 * ROWH + c1) * 2, Bp0 + (size_t)r1 * Kp + ko + c1);
            cp16(st + 3 * TILEB + (r0 * ROWH + c0) * 2, Bp1 + (size_t)r0 * Kp + ko + c0);
            cp16(st + 3 * TILEB + (r1 * ROWH + c1) * 2, Bp1 + (size_t)r1 * Kp + ko + c1);
            cp_commit();
            cp_wait1();
        } else cp_wait0();
        __syncthreads();

        uint32_t st = sm0 + (ci & 1) * 4 * TILEB;
        uint32_t aS0 = st, aS1 = st + TILEB, bS0 = st + 2 * TILEB, bS1 = st + 3 * TILEB;
#pragma unroll
        for (int kk = 0; kk < 2; kk++) {
            int k0 = kk * 16;
            uint32_t af[4][4], bf0[2][4], bf1[2][4];
#pragma unroll
            for (int np = 0; np < 2; np++) {
                ldsm4(bf0[np], bS0 + ((wn + np * 16 + rowOffB) * ROWH + k0 + colOffB) * 2);
                ldsm4(bf1[np], bS1 + ((wn + np * 16 + rowOffB) * ROWH + k0 + colOffB) * 2);
            }
#pragma unroll
            for (int mi = 0; mi < 4; mi++)
                ldsm4(af[mi], aS0 + ((wm + mi * 16 + rowOffA) * ROWH + k0 + colOffA) * 2);
#pragma unroll
            for (int mi = 0; mi < 4; mi++)
#pragma unroll
                for (int ni = 0; ni < 4; ni++) {
                    mma16816(acc[mi][ni], af[mi], &bf0[ni >> 1][(ni & 1) * 2]);
                    mma16816(acc[mi][ni], af[mi], &bf1[ni >> 1][(ni & 1) * 2]);
                }
#pragma unroll
            for (int mi = 0; mi < 4; mi++)
                ldsm4(af[mi], aS1 + ((wm + mi * 16 + rowOffA) * ROWH + k0 + colOffA) * 2);
#pragma unroll
            for (int mi = 0; mi < 4; mi++)
#pragma unroll
                for (int ni = 0; ni < 4; ni++)
                    mma16816(acc[mi][ni], af[mi], &bf0[ni >> 1][(ni & 1) * 2]);
        }
        __syncthreads();
    }

    float* Ob = Out + (size_t)bb * NPTS * (size_t)JS;
#pragma unroll
    for (int mi = 0; mi < 4; mi++) {
        int n0 = rowA + wm + mi * 16 + g, n1 = n0 + 8;
#pragma unroll
        for (int ni = 0; ni < 4; ni++) {
            int j0 = rowB + wn + ni * 8 + 2 * t4;
            *(float2*)&Ob[(size_t)n0 * JS + j0] = make_float2(acc[mi][ni][0], acc[mi][ni][1]);
            *(float2*)&Ob[(size_t)n1 * JS + j0] = make_float2(acc[mi][ni][2], acc[mi][ni][3]);
        }
    }
}

// ---------------- top-8 phase A: per-(row, 1024-col chunk) -------------------
__global__ void topkA_kernel(const float* __restrict__ D,
                             float* __restrict__ pv, int* __restrict__ pi) {
    int b = blockIdx.z, n = blockIdx.y, ch = blockIdx.x, tid = threadIdx.x;
    const float4* row = (const float4*)(D + ((size_t)b * NPTS + n) * NPTS) + ch * 256;
    float tv[NCAND]; int ti[NCAND];
#pragma unroll
    for (int j = 0; j < NCAND; j++) { tv[j] = NEGINF; ti[j] = 0x7fffffff; }
#pragma unroll
    for (int rr = 0; rr < 2; rr++) {
        int m4 = tid + rr * 128;
        float4 vv = row[m4];
        float va[4] = { vv.x, vv.y, vv.z, vv.w };
#pragma unroll
        for (int u = 0; u < 4; u++) {
            float v = va[u];
            if (v > tv[NCAND - 1]) {
                int m = ch * 1024 + m4 * 4 + u;
                int j = NCAND - 1;
                while (j > 0 && v > tv[j - 1]) { tv[j] = tv[j - 1]; ti[j] = ti[j - 1]; j--; }
                tv[j] = v; ti[j] = m;
            }
        }
    }
    __shared__ float sv[128];
    __shared__ int   si[128];
    __shared__ int   swin;
    int head = 0;
    size_t ob = (((size_t)b * NPTS + n) * NCHK + ch) * NCAND;
    for (int p = 0; p < NCAND; p++) {
        sv[tid] = (head < NCAND) ? tv[head] : NEGINF;
        si[tid] = (head < NCAND) ? ti[head] : 0x7fffffff;
        __syncthreads();
        if (tid < 32) {
            float bv = NEGINF;
            int bi = 0x7fffffff, bt = -1;
            for (int t = tid; t < 128; t += 32) {
                float v = sv[t]; int i2 = si[t];
                if (v > bv || (v == bv && i2 < bi)) { bv = v; bi = i2; bt = t; }
            }
            for (int off = 16; off; off >>= 1) {
                float ov = __shfl_down_sync(0xffffffffu, bv, off);
                int oi = __shfl_down_sync(0xffffffffu, bi, off);
                int ot = __shfl_down_sync(0xffffffffu, bt, off);
                if (ov > bv || (ov == bv && oi < bi)) { bv = ov; bi = oi; bt = ot; }
            }
            if (tid == 0) { pv[ob + p] = bv; pi[ob + p] = bi; swin = bt; }
        }
        __syncthreads();
        if (tid == swin) head++;
        __syncthreads();
    }
}

// ---------------- top-8 phase B: merge 32 -> 8 -------------------------------
__global__ void topkB_kernel(const float* __restrict__ pv, const int* __restrict__ pi,
                             int* __restrict__ cand) {
    int b = blockIdx.y, n = blockIdx.x, lane = threadIdx.x;
    size_t ib = ((size_t)b * NPTS + n) * (NCHK * NCAND);
    float v = pv[ib + lane];
    int   i = pi[ib + lane];
    int* co = cand + ((size_t)b * NPTS + n) * NCAND;
    for (int p = 0; p < NCAND; p++) {
        float bv = v; int bi = i; int bl = lane;
        for (int off = 16; off; off >>= 1) {
            float ov = __shfl_down_sync(0xffffffffu, bv, off);
            int oi = __shfl_down_sync(0xffffffffu, bi, off);
            int ol = __shfl_down_sync(0xffffffffu, bl, off);
            if (ov > bv || (ov == bv && oi < bi)) { bv = ov; bi = oi; bl = ol; }
        }
        bv = __shfl_sync(0xffffffffu, bv, 0);
        bi = __shfl_sync(0xffffffffu, bi, 0);
        bl = __shfl_sync(0xffffffffu, bl, 0);
        if (lane == 0) co[p] = bi;
        if (lane == bl) v = NEGINF;
    }
}

// ---------------- exact rescore: warp per candidate --------------------------
__global__ __launch_bounds__(256) void rescore_kernel(
    const float* __restrict__ X, const float* __restrict__ sq,
    const int* __restrict__ cand, int* __restrict__ idx, int Cdim) {
    int b = blockIdx.y, n = blockIdx.x, tid = threadIdx.x;
    int lane = tid & 31, wid = tid >> 5;
    __shared__ float xn[896];
    __shared__ float vals[NCAND];
    __shared__ int   vm[NCAND];
    const float* xrow = X + ((size_t)b * NPTS + n) * Cdim;
    for (int c = tid; c < Cdim; c += 256) xn[c] = xrow[c];
    __syncthreads();
    const float* sqb = sq + b * NPTS;
    float sn = sqb[n];
    int m = cand[((size_t)b * NPTS + n) * NCAND + wid];
    const float* xm = X + ((size_t)b * NPTS + m) * Cdim;
    double s = 0.0;
    for (int c = lane; c < Cdim; c += 32) s += (double)xn[c] * (double)xm[c];
    for (int off = 16; off; off >>= 1) s += __shfl_down_sync(0xffffffffu, s, off);
    if (lane == 0) {
        float Gf = (float)s;
        float t1 = __fadd_rn(sn, sqb[m]);
        vals[wid] = -__fadd_rn(t1, -__fmul_rn(2.0f, Gf));
        vm[wid] = m;
    }
    __syncthreads();
    if (tid == 0) {
        bool used[NCAND] = {};
        for (int p = 0; p < KNN; p++) {
            float bv = NEGINF; int bi = 0x7fffffff, bj = -1;
            for (int j = 0; j < NCAND; j++) {
                if (used[j]) continue;
                if (vals[j] > bv || (vals[j] == bv && vm[j] < bi)) { bv = vals[j]; bi = vm[j]; bj = j; }
            }
            used[bj] = true;
            idx[((size_t)b * NPTS + n) * KNN + p] = bi;
        }
    }
}

// ---------------- gather + max over k + BN + LeakyReLU (float4) --------------
__global__ void gathermax_kernel(const float* __restrict__ PQ, const int* __restrict__ idx,
                                 const float* __restrict__ gamma, const float* __restrict__ beta,
                                 const float* __restrict__ mean, const float* __restrict__ var,
                                 float* __restrict__ out, int OUT, int JS) {
    int b = blockIdx.y, n = blockIdx.x;
    __shared__ int nb[KNN];
    if (threadIdx.x < KNN) nb[threadIdx.x] = idx[((size_t)b * NPTS + n) * KNN + threadIdx.x];
    __syncthreads();
    const float* base = PQ + (size_t)b * NPTS * JS;
    const float4* p0 = (const float4*)(base + (size_t)nb[0] * JS);
    const float4* p1 = (const float4*)(base + (size_t)nb[1] * JS);
    const float4* p2 = (const float4*)(base + (size_t)nb[2] * JS);
    const float4* p3 = (const float4*)(base + (size_t)nb[3] * JS);
    const float4* p4 = (const float4*)(base + (size_t)nb[4] * JS);
    const float4* qv = (const float4*)(base + (size_t)n * JS + OUT);
    float4* orow = (float4*)(out + ((size_t)b * NPTS + n) * OUT);
    int n4 = OUT / 4;
    for (int o = threadIdx.x; o < n4; o += blockDim.x) {
        float4 a = p0[o], v1 = p1[o], v2 = p2[o], v3 = p3[o], v4 = p4[o], qq = qv[o];
        float4 gg = ((const float4*)gamma)[o], be = ((const float4*)beta)[o];
        float4 me = ((const float4*)mean)[o], va = ((const float4*)var)[o];
        float mx[4] = {
            fmaxf(fmaxf(fmaxf(a.x, v1.x), fmaxf(v2.x, v3.x)), v4.x),
            fmaxf(fmaxf(fmaxf(a.y, v1.y), fmaxf(v2.y, v3.y)), v4.y),
            fmaxf(fmaxf(fmaxf(a.z, v1.z), fmaxf(v2.z, v3.z)), v4.z),
            fmaxf(fmaxf(fmaxf(a.w, v1.w), fmaxf(v2.w, v3.w)), v4.w) };
        float qa[4] = { qq.x, qq.y, qq.z, qq.w };
        float ga[4] = { gg.x, gg.y, gg.z, gg.w }, ba[4] = { be.x, be.y, be.z, be.w };
        float ma[4] = { me.x, me.y, me.z, me.w }, vva[4] = { va.x, va.y, va.z, va.w };
        float4 res;
        float* rp = (float*)&res;
#pragma unroll
        for (int u = 0; u < 4; u++) {
            double h = (double)mx[u] + (double)qa[u];
            double sc = (double)ga[u] * rsqrt((double)vva[u] + 1e-5);
            double v = (h - (double)ma[u]) * sc + (double)ba[u];
            float vf = (float)v;
            rp[u] = (vf >= 0.f) ? vf : 0.2f * vf;
        }
        orow[o] = res;
    }
}

// ---------------- launcher ---------------------------------------------------
extern "C" void kernel_launch(void* const* d_in, const int* in_sizes, int n_in,
                              void* d_out, int out_size) {
    const float* X0 = (const float*)d_in[0];
    const float* W1 = (const float*)d_in[1];
    const float* g1 = (const float*)d_in[2];
    const float* b1 = (const float*)d_in[3];
    const float* m1 = (const float*)d_in[4];
    const float* v1 = (const float*)d_in[5];
    const float* W2 = (const float*)d_in[6];
    const float* g2 = (const float*)d_in[7];
    const float* b2 = (const float*)d_in[8];
    const float* m2 = (const float*)d_in[9];
    const float* v2 = (const float*)d_in[10];
    float* out = (float*)d_out;

    float *pD, *pPQ, *pX1, *pSq, *pPv;
    __nv_bfloat16 *pXA, *pWB;
    int *pIdx, *pCand, *pPi;
    cudaGetSymbolAddress((void**)&pD, g_D);
    cudaGetSymbolAddress((void**)&pPQ, g_PQ);
    cudaGetSymbolAddress((void**)&pX1, g_X1);
    cudaGetSymbolAddress((void**)&pXA, g_XA);
    cudaGetSymbolAddress((void**)&pWB, g_WB);
    cudaGetSymbolAddress((void**)&pSq, g_sq);
    cudaGetSymbolAddress((void**)&pIdx, g_idx);
    cudaGetSymbolAddress((void**)&pCand, g_cand);
    cudaGetSymbolAddress((void**)&pPv, g_pv);
    cudaGetSymbolAddress((void**)&pPi, g_pi);

    const int DSM_DIST = NSTAGE * 2 * TILEB;   // 102400
    const int DSM_PQ   = 2 * 4 * TILEB;        // 81920
    cudaFuncSetAttribute(dist_gemm_kernel, cudaFuncAttributeMaxDynamicSharedMemorySize, DSM_DIST);
    cudaFuncSetAttribute(pq_gemm_kernel, cudaFuncAttributeMaxDynamicSharedMemorySize, DSM_PQ);

    size_t aPlane1 = (size_t)BATCH * NPTS * KP1;
    size_t aPlane2 = (size_t)BATCH * NPTS * KP2;
    size_t wPlane  = (size_t)J2P * KP2;

    // ---- Layer 1 (Cin=512, OUT=864, JS=1792) ----
    rowsq_kernel<<<dim3(NPTS, BATCH), 128>>>(X0, pSq, C1);
    split3x_kernel<<<4096, 256>>>(X0, pXA, C1, KP1, aPlane1);
    splitW_kernel<<<2048, 256>>>(W1, pWB, C1, H1, KP1, wPlane);
    dist_gemm_kernel<<<dim3(32, 32, BATCH), 256, DSM_DIST>>>(
        pXA, (size_t)NPTS * KP1, KP1, pSq, pD);
    topkA_kernel<<<dim3(NCHK, NPTS, BATCH), 128>>>(pD, pPv, pPi);
    topkB_kernel<<<dim3(NPTS, BATCH), 32>>>(pPv, pPi, pCand);
    rescore_kernel<<<dim3(NPTS, BATCH), 256>>>(X0, pSq, pCand, pIdx, C1);
    pq_gemm_kernel<<<dim3(J1P / BN, 32, BATCH), 256, DSM_PQ>>>(
        pXA, pWB, aPlane1, wPlane, (size_t)NPTS * KP1, KP1, pPQ, J1P);
    gathermax_kernel<<<dim3(NPTS, BATCH), 256>>>(pPQ, pIdx, g1, b1, m1, v1, pX1, H1, J1P);

    // ---- Layer 2 (Cin=864 pad 896, OUT=1728, JS=3456) ----
    rowsq_kernel<<<dim3(NPTS, BATCH), 128>>>(pX1, pSq, H1);
    split3x_kernel<<<4096, 256>>>(pX1, pXA, H1, KP2, aPlane2);
    splitW_kernel<<<4096, 256>>>(W2, pWB, H1, H2, KP2, wPlane);
    dist_gemm_kernel<<<dim3(32, 32, BATCH), 256, DSM_DIST>>>(
        pXA, (size_t)NPTS * KP2, KP2, pSq, pD);
    topkA_kernel<<<dim3(NCHK, NPTS, BATCH), 128>>>(pD, pPv, pPi);
    topkB_kernel<<<dim3(NPTS, BATCH), 32>>>(pPv, pPi, pCand);
    rescore_kernel<<<dim3(NPTS, BATCH), 256>>>(pX1, pSq, pCand, pIdx, H1);
    pq_gemm_kernel<<<dim3(J2P / BN, 32, BATCH), 256, DSM_PQ>>>(
        pXA, pWB, aPlane2, wPlane, (size_t)NPTS * KP2, KP2, pPQ, J2P);
    gathermax_kernel<<<dim3(NPTS, BATCH), 256>>>(pPQ, pIdx, g2, b2, m2, v2, out, H2, J2P);
}

// round 15
// speedup vs baseline: 1.3374x; 1.0068x over previous
#include <cuda_runtime.h>
#include <cuda_bf16.h>
#include <cstdint>
#include <cstddef>

#define NPTS 4096
#define BATCH 4
#define C1 512
#define H1 864
#define H2 1728
#define KNN 5
#define NCAND 8
#define KP1 512
#define KP2 896
#define J1P 1792
#define J2P 3456

#define BM 128
#define BN 128
#define BKH 32
#define ROWH 40
#define NSTAGE 5
#define NCHK 4
#define TILEB (BM * ROWH * 2)     // 10240 bytes per 128x32h tile
#define DTS 132                   // transposed fp32 staging row stride

// ---------------- scratch (device globals) ----------------------------------
__device__ __align__(16) float g_D[(size_t)BATCH * NPTS * NPTS];
__device__ __align__(16) float g_PQ[(size_t)BATCH * NPTS * J2P];
__device__ __align__(16) float g_X1[(size_t)BATCH * NPTS * H1];
__device__ __align__(16) __nv_bfloat16 g_XA[(size_t)3 * BATCH * NPTS * KP2];
__device__ __align__(16) __nv_bfloat16 g_WB[(size_t)3 * J2P * KP2];
__device__ float g_sq[BATCH * NPTS];
__device__ int   g_idx[BATCH * NPTS * KNN];
__device__ int   g_cand[BATCH * NPTS * NCAND];
__device__ float g_pv[(size_t)BATCH * NPTS * NCHK * NCAND];
__device__ int   g_pi[(size_t)BATCH * NPTS * NCHK * NCAND];

// ---------------- helpers ----------------------------------------------------
__device__ __forceinline__ uint32_t smem_u32(const void* p) {
    uint32_t a;
    asm("{ .reg .u64 t; cvta.to.shared.u64 t, %1; cvt.u32.u64 %0, t; }" : "=r"(a) : "l"(p));
    return a;
}
__device__ __forceinline__ void cp16(uint32_t s, const void* g) {
    asm volatile("cp.async.cg.shared.global [%0], [%1], 16;" :: "r"(s), "l"(g));
}
__device__ __forceinline__ void cp_commit() { asm volatile("cp.async.commit_group;" ::: "memory"); }
__device__ __forceinline__ void cp_wait3()  { asm volatile("cp.async.wait_group 3;" ::: "memory"); }
__device__ __forceinline__ void cp_wait1()  { asm volatile("cp.async.wait_group 1;" ::: "memory"); }
__device__ __forceinline__ void cp_wait0()  { asm volatile("cp.async.wait_group 0;" ::: "memory"); }
__device__ __forceinline__ void ldsm4(uint32_t* r, uint32_t a) {
    asm volatile("ldmatrix.sync.aligned.m8n8.x4.shared.b16 {%0,%1,%2,%3}, [%4];"
        : "=r"(r[0]), "=r"(r[1]), "=r"(r[2]), "=r"(r[3]) : "r"(a));
}
__device__ __forceinline__ void mma16816(float* c, const uint32_t* a, const uint32_t* b) {
    asm volatile(
        "mma.sync.aligned.m16n8k16.row.col.f32.bf16.bf16.f32 "
        "{%0,%1,%2,%3}, {%4,%5,%6,%7}, {%8,%9}, {%0,%1,%2,%3};"
        : "+f"(c[0]), "+f"(c[1]), "+f"(c[2]), "+f"(c[3])
        : "r"(a[0]), "r"(a[1]), "r"(a[2]), "r"(a[3]), "r"(b[0]), "r"(b[1]));
}
#define NEGINF (-__int_as_float(0x7f800000))

// ---------------- small kernels ---------------------------------------------
__global__ void rowsq_kernel(const float* __restrict__ X, float* __restrict__ sq, int Cdim) {
    int b = blockIdx.y, n = blockIdx.x;
    const float* x = X + ((size_t)b * NPTS + n) * Cdim;
    double s = 0.0;
    for (int c = threadIdx.x; c < Cdim; c += 128) { float v = x[c]; s += (double)(v * v); }
    for (int off = 16; off; off >>= 1) s += __shfl_down_sync(0xffffffffu, s, off);
    __shared__ double red[4];
    if ((threadIdx.x & 31) == 0) red[threadIdx.x >> 5] = s;
    __syncthreads();
    if (threadIdx.x == 0) sq[b * NPTS + n] = (float)(red[0] + red[1] + red[2] + red[3]);
}

__global__ void split3x_kernel(const float* __restrict__ X, __nv_bfloat16* __restrict__ P,
                               int Cin, int Kp, size_t planeStride) {
    size_t total = (size_t)BATCH * NPTS * Kp;
    for (size_t t = (size_t)blockIdx.x * blockDim.x + threadIdx.x; t < total;
         t += (size_t)gridDim.x * blockDim.x) {
        size_t bn = t / Kp; int c = (int)(t - bn * Kp);
        float x = (c < Cin) ? X[bn * Cin + c] : 0.f;
        __nv_bfloat16 h0 = __float2bfloat16(x);
        float r1 = x - __bfloat162float(h0);
        __nv_bfloat16 h1 = __float2bfloat16(r1);
        float r2 = r1 - __bfloat162float(h1);
        P[t] = h0; P[planeStride + t] = h1; P[2 * planeStride + t] = __float2bfloat16(r2);
    }
}

__global__ void splitW_kernel(const float* __restrict__ W, __nv_bfloat16* __restrict__ P,
                              int Cin, int OUT, int Kp, size_t planeStride) {
    size_t total = (size_t)2 * OUT * Kp;
    for (size_t t = (size_t)blockIdx.x * blockDim.x + threadIdx.x; t < total;
         t += (size_t)gridDim.x * blockDim.x) {
        size_t j = t / Kp; int c = (int)(t - j * Kp);
        float w = 0.f;
        if (c < Cin) {
            if ((int)j < OUT) w = W[j * (2 * Cin) + c];
            else { size_t o = j - OUT; w = __fadd_rn(W[o * (2 * Cin) + Cin + c], -W[o * (2 * Cin) + c]); }
        }
        __nv_bfloat16 h0 = __float2bfloat16(w);
        float r1 = w - __bfloat162float(h0);
        __nv_bfloat16 h1 = __float2bfloat16(r1);
        float r2 = r1 - __bfloat162float(h1);
        P[t] = h0; P[planeStride + t] = h1; P[2 * planeStride + t] = __float2bfloat16(r2);
    }
}

// ---------------- distance GEMM (128x128, ldmatrix, 5-stage, fp32 D) ---------
__global__ __launch_bounds__(256, 2) void dist_gemm_kernel(
    const __nv_bfloat16* __restrict__ A0, size_t aBatch,
    int Kp, const float* __restrict__ sq, float* __restrict__ Out) {
    extern __shared__ __align__(16) char dyn[];
    __nv_bfloat16* smA = (__nv_bfloat16*)dyn;
    __nv_bfloat16* smB = (__nv_bfloat16*)(dyn + NSTAGE * TILEB);

    int tid = threadIdx.x;
    int bb = blockIdx.z;
    int br = blockIdx.y, bc = blockIdx.x;
    if (bc > br) return;
    int rowA = br * BM, rowB = bc * BN;

    const __nv_bfloat16* Ap = A0 + (size_t)bb * aBatch + (size_t)rowA * Kp;
    const __nv_bfloat16* Bp = A0 + (size_t)bb * aBatch + (size_t)rowB * Kp;

    int r0 = tid >> 2, c0 = (tid & 3) * 8;
    int r1 = (tid + 256) >> 2, c1 = ((tid + 256) & 3) * 8;

    int lane = tid & 31, wid = tid >> 5;
    int g = lane >> 2, t4 = lane & 3;
    int q = lane >> 3, lr = lane & 7;
    int wm = (wid >> 2) * 64, wn = (wid & 3) * 32;
    int rowOffA = (q & 1) * 8 + lr, colOffA = (q >> 1) * 8;
    int rowOffB = (q >> 1) * 8 + lr, colOffB = (q & 1) * 8;

    int nch = Kp >> 5;
    uint32_t sAu = smem_u32(smA), sBu = smem_u32(smB);

#pragma unroll
    for (int s = 0; s < NSTAGE - 1; s++) {
        int ko = s * BKH;
        uint32_t a = sAu + s * TILEB;
        uint32_t b = sBu + s * TILEB;
        cp16(a + (r0 * ROWH + c0) * 2, Ap + (size_t)r0 * Kp + ko + c0);
        cp16(a + (r1 * ROWH + c1) * 2, Ap + (size_t)r1 * Kp + ko + c1);
        cp16(b + (r0 * ROWH + c0) * 2, Bp + (size_t)r0 * Kp + ko + c0);
        cp16(b + (r1 * ROWH + c1) * 2, Bp + (size_t)r1 * Kp + ko + c1);
        cp_commit();
    }

    float acc[4][4][4];
#pragma unroll
    for (int mi = 0; mi < 4; mi++)
#pragma unroll
        for (int ni = 0; ni < 4; ni++)
#pragma unroll
            for (int p = 0; p < 4; p++) acc[mi][ni][p] = 0.f;

    int stage = 0;
    for (int ci = 0; ci < nch; ci++) {
        cp_wait3();
        __syncthreads();
        uint32_t aS = sAu + stage * TILEB;
        uint32_t bS = sBu + stage * TILEB;
#pragma unroll
        for (int kk = 0; kk < 2; kk++) {
            int k0 = kk * 16;
            uint32_t af[4][4], bfr[2][4];
#pragma unroll
            for (int mi = 0; mi < 4; mi++)
                ldsm4(af[mi], aS + ((wm + mi * 16 + rowOffA) * ROWH + k0 + colOffA) * 2);
#pragma unroll
            for (int np = 0; np < 2; np++)
                ldsm4(bfr[np], bS + ((wn + np * 16 + rowOffB) * ROWH + k0 + colOffB) * 2);
#pragma unroll
            for (int mi = 0; mi < 4; mi++)
#pragma unroll
                for (int ni = 0; ni < 4; ni++)
                    mma16816(acc[mi][ni], af[mi], &bfr[ni >> 1][(ni & 1) * 2]);
        }
        int nb = ci + NSTAGE - 1;
        if (nb < nch) {
            int ko = nb * BKH;
            int st2 = nb % NSTAGE;
            uint32_t a = sAu + st2 * TILEB;
            uint32_t b = sBu + st2 * TILEB;
            cp16(a + (r0 * ROWH + c0) * 2, Ap + (size_t)r0 * Kp + ko + c0);
            cp16(a + (r1 * ROWH + c1) * 2, Ap + (size_t)r1 * Kp + ko + c1);
            cp16(b + (r0 * ROWH + c0) * 2, Bp + (size_t)r0 * Kp + ko + c0);
            cp16(b + (r1 * ROWH + c1) * 2, Bp + (size_t)r1 * Kp + ko + c1);
        }
        cp_commit();
        stage = (stage + 1 == NSTAGE) ? 0 : stage + 1;
    }

    // ---- epilogue: direct fp32 row stores + staged transposed mirror --------
    const float* sqb = sq + bb * NPTS;
    float* Db = Out + (size_t)bb * NPTS * NPTS;
    bool mirror = (br != bc);
    float* Dt2 = (float*)dyn;   // 128 x 132 fp32 transposed tile (67.6 KB)
    __syncthreads();            // all warps done with pipeline smem

#pragma unroll
    for (int mi = 0; mi < 4; mi++) {
        int rr0 = wm + mi * 16 + g;
        int rr1 = rr0 + 8;
        int n0 = rowA + rr0, n1 = rowA + rr1;
        float sn0 = sqb[n0], sn1 = sqb[n1];
#pragma unroll
        for (int ni = 0; ni < 4; ni++) {
            int cloc = wn + ni * 8 + 2 * t4;
            int m0 = rowB + cloc;
            float sm0 = sqb[m0], sm1 = sqb[m0 + 1];
            float v00 = -__fadd_rn(__fadd_rn(sn0, sm0), -__fmul_rn(2.0f, acc[mi][ni][0]));
            float v01 = -__fadd_rn(__fadd_rn(sn0, sm1), -__fmul_rn(2.0f, acc[mi][ni][1]));
            float v10 = -__fadd_rn(__fadd_rn(sn1, sm0), -__fmul_rn(2.0f, acc[mi][ni][2]));
            float v11 = -__fadd_rn(__fadd_rn(sn1, sm1), -__fmul_rn(2.0f, acc[mi][ni][3]));
            *(float2*)&Db[(size_t)n0 * NPTS + m0] = make_float2(v00, v01);
            *(float2*)&Db[(size_t)n1 * NPTS + m0] = make_float2(v10, v11);
            if (mirror) {
                Dt2[(cloc) * DTS + rr0]     = v00;
                Dt2[(cloc + 1) * DTS + rr0] = v01;
                Dt2[(cloc) * DTS + rr1]     = v10;
                Dt2[(cloc + 1) * DTS + rr1] = v11;
            }
        }
    }
    if (mirror) {
        __syncthreads();
        // write out transposed tile: Dt2 row c -> Db row (rowB+c), cols rowA..rowA+127
        int cbase = tid >> 5, j = tid & 31;   // 8 rows per iter, 32 lanes x 16B = 512B row
#pragma unroll
        for (int it = 0; it < 16; it++) {
            int c = cbase + it * 8;
            uint4 v = *(const uint4*)(Dt2 + c * DTS + j * 4);
            *(uint4*)&Db[(size_t)(rowB + c) * NPTS + rowA + j * 4] = v;
        }
    }
}

// ---------------- PQ GEMM: fused 3-term (A0,A1,B0,B1 per chunk) --------------
__global__ __launch_bounds__(256, 2) void pq_gemm_kernel(
    const __nv_bfloat16* __restrict__ Ag, const __nv_bfloat16* __restrict__ Bg,
    size_t aPlane, size_t bPlane, size_t aBatch,
    int Kp, float* __restrict__ Out, int JS) {
    extern __shared__ __align__(16) char dyn[];
    int tid = threadIdx.x;
    int bb = blockIdx.z;
    int rowA = blockIdx.y * BM, rowB = blockIdx.x * BN;

    const __nv_bfloat16* Ap0 = Ag + (size_t)bb * aBatch + (size_t)rowA * Kp;
    const __nv_bfloat16* Ap1 = Ap0 + aPlane;
    const __nv_bfloat16* Bp0 = Bg + (size_t)rowB * Kp;
    const __nv_bfloat16* Bp1 = Bp0 + bPlane;

    int r0 = tid >> 2, c0 = (tid & 3) * 8;
    int r1 = (tid + 256) >> 2, c1 = ((tid + 256) & 3) * 8;

    int lane = tid & 31, wid = tid >> 5;
    int g = lane >> 2, t4 = lane & 3;
    int q = lane >> 3, lr = lane & 7;
    int wm = (wid >> 2) * 64, wn = (wid & 3) * 32;
    int rowOffA = (q & 1) * 8 + lr, colOffA = (q >> 1) * 8;
    int rowOffB = (q >> 1) * 8 + lr, colOffB = (q & 1) * 8;

    int nch = Kp >> 5;
    uint32_t sm0 = smem_u32(dyn);

    {
        uint32_t st = sm0;
        cp16(st + 0 * TILEB + (r0 * ROWH + c0) * 2, Ap0 + (size_t)r0 * Kp + c0);
        cp16(st + 0 * TILEB + (r1 * ROWH + c1) * 2, Ap0 + (size_t)r1 * Kp + c1);
        cp16(st + 1 * TILEB + (r0 * ROWH + c0) * 2, Ap1 + (size_t)r0 * Kp + c0);
        cp16(st + 1 * TILEB + (r1 * ROWH + c1) * 2, Ap1 + (size_t)r1 * Kp + c1);
        cp16(st + 2 * TILEB + (r0 * ROWH + c0) * 2, Bp0 + (size_t)r0 * Kp + c0);
        cp16(st + 2 * TILEB + (r1 * ROWH + c1) * 2, Bp0 + (size_t)r1 * Kp + c1);
        cp16(st + 3 * TILEB + (r0 * ROWH + c0) * 2, Bp1 + (size_t)r0 * Kp + c0);
        cp16(st + 3 * TILEB + (r1 * ROWH + c1) * 2, Bp1 + (size_t)r1 * Kp + c1);
        cp_commit();
    }

    float acc[4][4][4];
#pragma unroll
    for (int mi = 0; mi < 4; mi++)
#pragma unroll
        for (int ni = 0; ni < 4; ni++)
#pragma unroll
            for (int p = 0; p < 4; p++) acc[mi][ni][p] = 0.f;

    for (int ci = 0; ci < nch; ci++) {
        int nb = ci + 1;
        if (nb < nch) {
            int ko = nb * BKH;
            uint32_t st = sm0 + (nb & 1) * 4 * TILEB;
            cp16(st + 0 * TILEB + (r0 * ROWH + c0) * 2, Ap0 + (size_t)r0 * Kp + ko + c0);
            cp16(st + 0 * TILEB + (r1 * ROWH + c1) * 2, Ap0 + (size_t)r1 * Kp + ko + c1);
            cp16(st + 1 * TILEB + (r0 * ROWH + c0) * 2, Ap1 + (size_t)r0 * Kp + ko + c0);
            cp16(st + 1 * TILEB + (r1 * ROWH + c1) * 2, Ap1 + (size_t)r1 * Kp + ko + c1);
            cp16(st + 2 * TILEB + (r0 * ROWH + c0) * 2, Bp0 + (size_t)r0 * Kp + ko + c0);
            cp16(st + 2 * TILEB + (r1 * ROWH + c1) * 2, Bp0 + (size_t)r1 * Kp + ko + c1);
            cp16(st + 3 * TILEB + (r0 * ROWH + c0) * 2, Bp1 + (size_t)r0 * Kp + ko + c0);
            cp16(st + 3 * TILEB + (r1 * ROWH + c1) * 2, Bp1 + (size_t)r1 * Kp + ko + c1);
            cp_commit();
            cp_wait1();
        } else cp_wait0();
        __syncthreads();

        uint32_t st = sm0 + (ci & 1) * 4 * TILEB;
        uint32_t aS0 = st, aS1 = st + TILEB, bS0 = st + 2 * TILEB, bS1 = st + 3 * TILEB;
#pragma unroll
        for (int kk = 0; kk < 2; kk++) {
            int k0 = kk * 16;
            uint32_t af[4][4], bf0[2][4], bf1[2][4];
#pragma unroll
            for (int np = 0; np < 2; np++) {
                ldsm4(bf0[np], bS0 + ((wn + np * 16 + rowOffB) * ROWH + k0 + colOffB) * 2);
                ldsm4(bf1[np], bS1 + ((wn + np * 16 + rowOffB) * ROWH + k0 + colOffB) * 2);
            }
#pragma unroll
            for (int mi = 0; mi < 4; mi++)
                ldsm4(af[mi], aS0 + ((wm + mi * 16 + rowOffA) * ROWH + k0 + colOffA) * 2);
#pragma unroll
            for (int mi = 0; mi < 4; mi++)
#pragma unroll
                for (int ni = 0; ni < 4; ni++) {
                    mma16816(acc[mi][ni], af[mi], &bf0[ni >> 1][(ni & 1) * 2]);
                    mma16816(acc[mi][ni], af[mi], &bf1[ni >> 1][(ni & 1) * 2]);
                }
#pragma unroll
            for (int mi = 0; mi < 4; mi++)
                ldsm4(af[mi], aS1 + ((wm + mi * 16 + rowOffA) * ROWH + k0 + colOffA) * 2);
#pragma unroll
            for (int mi = 0; mi < 4; mi++)
#pragma unroll
                for (int ni = 0; ni < 4; ni++)
                    mma16816(acc[mi][ni], af[mi], &bf0[ni >> 1][(ni & 1) * 2]);
        }
        __syncthreads();
    }

    float* Ob = Out + (size_t)bb * NPTS * (size_t)JS;
#pragma unroll
    for (int mi = 0; mi < 4; mi++) {
        int n0 = rowA + wm + mi * 16 + g, n1 = n0 + 8;
#pragma unroll
        for (int ni = 0; ni < 4; ni++) {
            int j0 = rowB + wn + ni * 8 + 2 * t4;
            *(float2*)&Ob[(size_t)n0 * JS + j0] = make_float2(acc[mi][ni][0], acc[mi][ni][1]);
            *(float2*)&Ob[(size_t)n1 * JS + j0] = make_float2(acc[mi][ni][2], acc[mi][ni][3]);
        }
    }
}

// ---------------- top-8 phase A: per-(row, 1024-col chunk) -------------------
__global__ void topkA_kernel(const float* __restrict__ D,
                             float* __restrict__ pv, int* __restrict__ pi) {
    int b = blockIdx.z, n = blockIdx.y, ch = blockIdx.x, tid = threadIdx.x;
    const float4* row = (const float4*)(D + ((size_t)b * NPTS + n) * NPTS) + ch * 256;
    float tv[NCAND]; int ti[NCAND];
#pragma unroll
    for (int j = 0; j < NCAND; j++) { tv[j] = NEGINF; ti[j] = 0x7fffffff; }
#pragma unroll
    for (int rr = 0; rr < 2; rr++) {
        int m4 = tid + rr * 128;
        float4 vv = row[m4];
        float va[4] = { vv.x, vv.y, vv.z, vv.w };
#pragma unroll
        for (int u = 0; u < 4; u++) {
            float v = va[u];
            if (v > tv[NCAND - 1]) {
                int m = ch * 1024 + m4 * 4 + u;
                int j = NCAND - 1;
                while (j > 0 && v > tv[j - 1]) { tv[j] = tv[j - 1]; ti[j] = ti[j - 1]; j--; }
                tv[j] = v; ti[j] = m;
            }
        }
    }
    __shared__ float sv[128];
    __shared__ int   si[128];
    __shared__ int   swin;
    int head = 0;
    size_t ob = (((size_t)b * NPTS + n) * NCHK + ch) * NCAND;
    for (int p = 0; p < NCAND; p++) {
        sv[tid] = (head < NCAND) ? tv[head] : NEGINF;
        si[tid] = (head < NCAND) ? ti[head] : 0x7fffffff;
        __syncthreads();
        if (tid < 32) {
            float bv = NEGINF;
            int bi = 0x7fffffff, bt = -1;
            for (int t = tid; t < 128; t += 32) {
                float v = sv[t]; int i2 = si[t];
                if (v > bv || (v == bv && i2 < bi)) { bv = v; bi = i2; bt = t; }
            }
            for (int off = 16; off; off >>= 1) {
                float ov = __shfl_down_sync(0xffffffffu, bv, off);
                int oi = __shfl_down_sync(0xffffffffu, bi, off);
                int ot = __shfl_down_sync(0xffffffffu, bt, off);
                if (ov > bv || (ov == bv && oi < bi)) { bv = ov; bi = oi; bt = ot; }
            }
            if (tid == 0) { pv[ob + p] = bv; pi[ob + p] = bi; swin = bt; }
        }
        __syncthreads();
        if (tid == swin) head++;
        __syncthreads();
    }
}

// ---------------- top-8 phase B: merge 32 -> 8 -------------------------------
__global__ void topkB_kernel(const float* __restrict__ pv, const int* __restrict__ pi,
                             int* __restrict__ cand) {
    int b = blockIdx.y, n = blockIdx.x, lane = threadIdx.x;
    size_t ib = ((size_t)b * NPTS + n) * (NCHK * NCAND);
    float v = pv[ib + lane];
    int   i = pi[ib + lane];
    int* co = cand + ((size_t)b * NPTS + n) * NCAND;
    for (int p = 0; p < NCAND; p++) {
        float bv = v; int bi = i; int bl = lane;
        for (int off = 16; off; off >>= 1) {
            float ov = __shfl_down_sync(0xffffffffu, bv, off);
            int oi = __shfl_down_sync(0xffffffffu, bi, off);
            int ol = __shfl_down_sync(0xffffffffu, bl, off);
            if (ov > bv || (ov == bv && oi < bi)) { bv = ov; bi = oi; bl = ol; }
        }
        bv = __shfl_sync(0xffffffffu, bv, 0);
        bi = __shfl_sync(0xffffffffu, bi, 0);
        bl = __shfl_sync(0xffffffffu, bl, 0);
        if (lane == 0) co[p] = bi;
        if (lane == bl) v = NEGINF;
    }
}

// ---------------- exact rescore: warp per candidate --------------------------
__global__ __launch_bounds__(256) void rescore_kernel(
    const float* __restrict__ X, const float* __restrict__ sq,
    const int* __restrict__ cand, int* __restrict__ idx, int Cdim) {
    int b = blockIdx.y, n = blockIdx.x, tid = threadIdx.x;
    int lane = tid & 31, wid = tid >> 5;
    __shared__ float xn[896];
    __shared__ float vals[NCAND];
    __shared__ int   vm[NCAND];
    const float* xrow = X + ((size_t)b * NPTS + n) * Cdim;
    for (int c = tid; c < Cdim; c += 256) xn[c] = xrow[c];
    __syncthreads();
    const float* sqb = sq + b * NPTS;
    float sn = sqb[n];
    int m = cand[((size_t)b * NPTS + n) * NCAND + wid];
    const float* xm = X + ((size_t)b * NPTS + m) * Cdim;
    double s = 0.0;
    for (int c = lane; c < Cdim; c += 32) s += (double)xn[c] * (double)xm[c];
    for (int off = 16; off; off >>= 1) s += __shfl_down_sync(0xffffffffu, s, off);
    if (lane == 0) {
        float Gf = (float)s;
        float t1 = __fadd_rn(sn, sqb[m]);
        vals[wid] = -__fadd_rn(t1, -__fmul_rn(2.0f, Gf));
        vm[wid] = m;
    }
    __syncthreads();
    if (tid == 0) {
        bool used[NCAND] = {};
        for (int p = 0; p < KNN; p++) {
            float bv = NEGINF; int bi = 0x7fffffff, bj = -1;
            for (int j = 0; j < NCAND; j++) {
                if (used[j]) continue;
                if (vals[j] > bv || (vals[j] == bv && vm[j] < bi)) { bv = vals[j]; bi = vm[j]; bj = j; }
            }
            used[bj] = true;
            idx[((size_t)b * NPTS + n) * KNN + p] = bi;
        }
    }
}

// ---------------- gather + max over k + BN + LeakyReLU (float4) --------------
__global__ void gathermax_kernel(const float* __restrict__ PQ, const int* __restrict__ idx,
                                 const float* __restrict__ gamma, const float* __restrict__ beta,
                                 const float* __restrict__ mean, const float* __restrict__ var,
                                 float* __restrict__ out, int OUT, int JS) {
    int b = blockIdx.y, n = blockIdx.x;
    __shared__ int nb[KNN];
    if (threadIdx.x < KNN) nb[threadIdx.x] = idx[((size_t)b * NPTS + n) * KNN + threadIdx.x];
    __syncthreads();
    const float* base = PQ + (size_t)b * NPTS * JS;
    const float4* p0 = (const float4*)(base + (size_t)nb[0] * JS);
    const float4* p1 = (const float4*)(base + (size_t)nb[1] * JS);
    const float4* p2 = (const float4*)(base + (size_t)nb[2] * JS);
    const float4* p3 = (const float4*)(base + (size_t)nb[3] * JS);
    const float4* p4 = (const float4*)(base + (size_t)nb[4] * JS);
    const float4* qv = (const float4*)(base + (size_t)n * JS + OUT);
    float4* orow = (float4*)(out + ((size_t)b * NPTS + n) * OUT);
    int n4 = OUT / 4;
    for (int o = threadIdx.x; o < n4; o += blockDim.x) {
        float4 a = p0[o], v1 = p1[o], v2 = p2[o], v3 = p3[o], v4 = p4[o], qq = qv[o];
        float4 gg = ((const float4*)gamma)[o], be = ((const float4*)beta)[o];
        float4 me = ((const float4*)mean)[o], va = ((const float4*)var)[o];
        float mx[4] = {
            fmaxf(fmaxf(fmaxf(a.x, v1.x), fmaxf(v2.x, v3.x)), v4.x),
            fmaxf(fmaxf(fmaxf(a.y, v1.y), fmaxf(v2.y, v3.y)), v4.y),
            fmaxf(fmaxf(fmaxf(a.z, v1.z), fmaxf(v2.z, v3.z)), v4.z),
            fmaxf(fmaxf(fmaxf(a.w, v1.w), fmaxf(v2.w, v3.w)), v4.w) };
        float qa[4] = { qq.x, qq.y, qq.z, qq.w };
        float ga[4] = { gg.x, gg.y, gg.z, gg.w }, ba[4] = { be.x, be.y, be.z, be.w };
        float ma[4] = { me.x, me.y, me.z, me.w }, vva[4] = { va.x, va.y, va.z, va.w };
        float4 res;
        float* rp = (float*)&res;
#pragma unroll
        for (int u = 0; u < 4; u++) {
            double h = (double)mx[u] + (double)qa[u];
            double sc = (double)ga[u] * rsqrt((double)vva[u] + 1e-5);
            double v = (h - (double)ma[u]) * sc + (double)ba[u];
            float vf = (float)v;
            rp[u] = (vf >= 0.f) ? vf : 0.2f * vf;
        }
        orow[o] = res;
    }
}

// ---------------- launcher ---------------------------------------------------
extern "C" void kernel_launch(void* const* d_in, const int* in_sizes, int n_in,
                              void* d_out, int out_size) {
    const float* X0 = (const float*)d_in[0];
    const float* W1 = (const float*)d_in[1];
    const float* g1 = (const float*)d_in[2];
    const float* b1 = (const float*)d_in[3];
    const float* m1 = (const float*)d_in[4];
    const float* v1 = (const float*)d_in[5];
    const float* W2 = (const float*)d_in[6];
    const float* g2 = (const float*)d_in[7];
    const float* b2 = (const float*)d_in[8];
    const float* m2 = (const float*)d_in[9];
    const float* v2 = (const float*)d_in[10];
    float* out = (float*)d_out;

    float *pD, *pPQ, *pX1, *pSq, *pPv;
    __nv_bfloat16 *pXA, *pWB;
    int *pIdx, *pCand, *pPi;
    cudaGetSymbolAddress((void**)&pD, g_D);
    cudaGetSymbolAddress((void**)&pPQ, g_PQ);
    cudaGetSymbolAddress((void**)&pX1, g_X1);
    cudaGetSymbolAddress((void**)&pXA, g_XA);
    cudaGetSymbolAddress((void**)&pWB, g_WB);
    cudaGetSymbolAddress((void**)&pSq, g_sq);
    cudaGetSymbolAddress((void**)&pIdx, g_idx);
    cudaGetSymbolAddress((void**)&pCand, g_cand);
    cudaGetSymbolAddress((void**)&pPv, g_pv);
    cudaGetSymbolAddress((void**)&pPi, g_pi);

    const int DSM_DIST = NSTAGE * 2 * TILEB;   // 102400 (>= 128*132*4 = 67584 staging)
    const int DSM_PQ   = 2 * 4 * TILEB;        // 81920
    cudaFuncSetAttribute(dist_gemm_kernel, cudaFuncAttributeMaxDynamicSharedMemorySize, DSM_DIST);
    cudaFuncSetAttribute(pq_gemm_kernel, cudaFuncAttributeMaxDynamicSharedMemorySize, DSM_PQ);

    size_t aPlane1 = (size_t)BATCH * NPTS * KP1;
    size_t aPlane2 = (size_t)BATCH * NPTS * KP2;
    size_t wPlane  = (size_t)J2P * KP2;

    // ---- Layer 1 (Cin=512, OUT=864, JS=1792) ----
    rowsq_kernel<<<dim3(NPTS, BATCH), 128>>>(X0, pSq, C1);
    split3x_kernel<<<4096, 256>>>(X0, pXA, C1, KP1, aPlane1);
    splitW_kernel<<<2048, 256>>>(W1, pWB, C1, H1, KP1, wPlane);
    dist_gemm_kernel<<<dim3(32, 32, BATCH), 256, DSM_DIST>>>(
        pXA, (size_t)NPTS * KP1, KP1, pSq, pD);
    topkA_kernel<<<dim3(NCHK, NPTS, BATCH), 128>>>(pD, pPv, pPi);
    topkB_kernel<<<dim3(NPTS, BATCH), 32>>>(pPv, pPi, pCand);
    rescore_kernel<<<dim3(NPTS, BATCH), 256>>>(X0, pSq, pCand, pIdx, C1);
    pq_gemm_kernel<<<dim3(J1P / BN, 32, BATCH), 256, DSM_PQ>>>(
        pXA, pWB, aPlane1, wPlane, (size_t)NPTS * KP1, KP1, pPQ, J1P);
    gathermax_kernel<<<dim3(NPTS, BATCH), 256>>>(pPQ, pIdx, g1, b1, m1, v1, pX1, H1, J1P);

    // ---- Layer 2 (Cin=864 pad 896, OUT=1728, JS=3456) ----
    rowsq_kernel<<<dim3(NPTS, BATCH), 128>>>(pX1, pSq, H1);
    split3x_kernel<<<4096, 256>>>(pX1, pXA, H1, KP2, aPlane2);
    splitW_kernel<<<4096, 256>>>(W2, pWB, H1, H2, KP2, wPlane);
    dist_gemm_kernel<<<dim3(32, 32, BATCH), 256, DSM_DIST>>>(
        pXA, (size_t)NPTS * KP2, KP2, pSq, pD);
    topkA_kernel<<<dim3(NCHK, NPTS, BATCH), 128>>>(pD, pPv, pPi);
    topkB_kernel<<<dim3(NPTS, BATCH), 32>>>(pPv, pPi, pCand);
    rescore_kernel<<<dim3(NPTS, BATCH), 256>>>(pX1, pSq, pCand, pIdx, H1);
    pq_gemm_kernel<<<dim3(J2P / BN, 32, BATCH), 256, DSM_PQ>>>(
        pXA, pWB, aPlane2, wPlane, (size_t)NPTS * KP2, KP2, pPQ, J2P);
    gathermax_kernel<<<dim3(NPTS, BATCH), 256>>>(pPQ, pIdx, g2, b2, m2, v2, out, H2, J2P);
}